// round 15
// baseline (speedup 1.0000x reference)
#include <cuda_runtime.h>
#include <math.h>

#define Sd 262144
#define BN_CNT 524288.0

#define MH   0x1FFFFFFu
#define MFZ  0x7FFFFFu
#define MFYZ 0x1FFFFFu
#define MXF  0x7FFFFu

typedef unsigned long long ull;

__device__ __align__(16) float g_H [1u<<25];
__device__ __align__(16) float g_Y [1u<<25];
__device__ __align__(16) float g_FZ [1u<<23];
__device__ __align__(16) float g_FYZ[1u<<21];
__device__ __align__(16) float g_XF [1u<<19];
__device__ __align__(16) float g_XO [1u<<19];
__device__ __align__(16) float g_GX [1u<<21];
__device__ __align__(16) float g_WP [1u<<23];
__device__ double g_acc[128];

__device__ __forceinline__ float ldc(const float* p, long i, long n) {
    return (i >= 0 && i < n) ? p[i] : 0.0f;
}
__device__ __forceinline__ ull pk(float x, float y) {
    ull r; asm("mov.b64 %0, {%1,%2};" : "=l"(r) : "f"(x), "f"(y)); return r;
}
__device__ __forceinline__ void upk(ull v, float& x, float& y) {
    asm("mov.b64 {%0,%1}, %2;" : "=f"(x), "=f"(y) : "l"(v));
}
__device__ __forceinline__ ull fma2(ull a, ull b, ull c) {
    ull d; asm("fma.rn.f32x2 %0, %1, %2, %3;" : "=l"(d) : "l"(a), "l"(b), "l"(c)); return d;
}

__global__ void zero_acc_k() { g_acc[threadIdx.x & 127] = 0.0; }

// fused fc0 + conv1x1(block0) + BN stats. grid 2048, block 256
__global__ void fc0conv_k(const float* __restrict__ xin, long nx,
                          const float* __restrict__ w, long nw,
                          const float* __restrict__ bias, long nb,
                          const float* __restrict__ cw, long ncwn,
                          const float* __restrict__ cb, long ncb) {
    __shared__ __align__(16) float wt[512];
    __shared__ __align__(16) float cws[1024];
    __shared__ float bs[32], cbs[32], s1[64], s2[64];
    int tid = threadIdx.x;
    for (int i = tid; i < 512; i += 256) {
        int o = i >> 4, ii = i & 15;
        wt[i] = (ii < 13) ? ldc(w, ii*32 + o, nw) : 0.0f;
    }
    for (int i = tid; i < 1024; i += 256) cws[i] = ldc(cw, i, ncwn);
    if (tid < 32) { bs[tid] = ldc(bias, tid, nb); cbs[tid] = ldc(cb, tid, ncb); }
    if (tid < 64) { s1[tid] = 0.f; s2[tid] = 0.f; }
    __syncthreads();
    int p = blockIdx.x * 256 + tid;
    int b = (p >> 18) & 1, s = p & (Sd - 1);
    long off = (long)p * 26;
    float h0[32], h1[32];
    {
        float v0[13], v1[13];
        #pragma unroll
        for (int i = 0; i < 13; i++) { v0[i] = ldc(xin, off + i, nx); v1[i] = ldc(xin, off + 13 + i, nx); }
        #pragma unroll
        for (int o = 0; o < 32; o++) {
            float a0 = bs[o], a1 = bs[o];
            #pragma unroll
            for (int i4 = 0; i4 < 3; i4++) {
                float4 wv = *(const float4*)&wt[o*16 + i4*4];
                a0 += v0[i4*4+0]*wv.x + v0[i4*4+1]*wv.y + v0[i4*4+2]*wv.z + v0[i4*4+3]*wv.w;
                a1 += v1[i4*4+0]*wv.x + v1[i4*4+1]*wv.y + v1[i4*4+2]*wv.z + v1[i4*4+3]*wv.w;
            }
            a0 += v0[12]*wt[o*16+12];
            a1 += v1[12]*wt[o*16+12];
            h0[o] = a0; h1[o] = a1;
            g_H[((unsigned)((0*2 + b)*32 + o)*Sd + s) & MH] = a0;
            g_H[((unsigned)((1*2 + b)*32 + o)*Sd + s) & MH] = a1;
        }
    }
    int lane = tid & 31;
    #pragma unroll
    for (int o = 0; o < 32; o++) {
        float y0 = cbs[o], y1 = cbs[o];
        #pragma unroll
        for (int c4 = 0; c4 < 8; c4++) {
            float4 wv = *(const float4*)&cws[o*32 + c4*4];
            y0 += h0[c4*4+0]*wv.x + h0[c4*4+1]*wv.y + h0[c4*4+2]*wv.z + h0[c4*4+3]*wv.w;
            y1 += h1[c4*4+0]*wv.x + h1[c4*4+1]*wv.y + h1[c4*4+2]*wv.z + h1[c4*4+3]*wv.w;
        }
        g_Y[((unsigned)((0*2 + b)*32 + o)*Sd + s) & MH] = y0;
        g_Y[((unsigned)((1*2 + b)*32 + o)*Sd + s) & MH] = y1;
        float r0 = y0, q0 = y0*y0, r1 = y1, q1 = y1*y1;
        #pragma unroll
        for (int ofs = 16; ofs; ofs >>= 1) {
            r0 += __shfl_down_sync(0xffffffffu, r0, ofs);
            q0 += __shfl_down_sync(0xffffffffu, q0, ofs);
            r1 += __shfl_down_sync(0xffffffffu, r1, ofs);
            q1 += __shfl_down_sync(0xffffffffu, q1, ofs);
        }
        if (lane == 0) {
            atomicAdd(&s1[o], r0); atomicAdd(&s2[o], q0);
            atomicAdd(&s1[32 + o], r1); atomicAdd(&s2[32 + o], q1);
        }
    }
    __syncthreads();
    if (tid < 64) {
        atomicAdd(&g_acc[(tid*2 + 0) & 127], (double)s1[tid]);
        atomicAdd(&g_acc[(tid*2 + 1) & 127], (double)s2[tid]);
    }
}

// 1x1 conv + BN stats, 2 points/thread, o-pair packed FFMA2. grid (512,4), block 256
__global__ void convB_k(const float* __restrict__ w, long nw,
                        const float* __restrict__ bias, long nb) {
    __shared__ __align__(16) float ws[1024];
    __shared__ __align__(16) ulonglong2 wq[256];
    __shared__ float bs[32], s1[32], s2[32];
    int tid = threadIdx.x;
    for (int i = tid; i < 1024; i += 256) ws[i] = ldc(w, i, nw);
    if (tid < 32) { bs[tid] = ldc(bias, tid, nb); s1[tid] = 0.f; s2[tid] = 0.f; }
    __syncthreads();
    {
        int o4 = tid >> 5, c = tid & 31;
        ulonglong2 q;
        q.x = pk(ws[(o4*4+0)*32 + c], ws[(o4*4+1)*32 + c]);
        q.y = pk(ws[(o4*4+2)*32 + c], ws[(o4*4+3)*32 + c]);
        wq[tid] = q;
    }
    __syncthreads();
    int nbk = blockIdx.y;
    int s0 = (blockIdx.x * 256 + tid) * 2;
    unsigned base = (unsigned)nbk * 32u * Sd + (unsigned)s0;
    ull a0[16], a1[16];
    #pragma unroll
    for (int o4 = 0; o4 < 8; o4++) {
        a0[o4*2]   = pk(bs[o4*4+0], bs[o4*4+1]);
        a0[o4*2+1] = pk(bs[o4*4+2], bs[o4*4+3]);
        a1[o4*2]   = a0[o4*2];
        a1[o4*2+1] = a0[o4*2+1];
    }
    #pragma unroll
    for (int c = 0; c < 32; c++) {
        ull vp = *(const ull*)&g_H[(base + (unsigned)c * Sd) & MH];
        float vx, vy; upk(vp, vx, vy);
        ull d0 = pk(vx, vx), d1 = pk(vy, vy);
        #pragma unroll
        for (int o4 = 0; o4 < 8; o4++) {
            ulonglong2 w2 = wq[o4*32 + c];
            a0[o4*2]   = fma2(d0, w2.x, a0[o4*2]);
            a0[o4*2+1] = fma2(d0, w2.y, a0[o4*2+1]);
            a1[o4*2]   = fma2(d1, w2.x, a1[o4*2]);
            a1[o4*2+1] = fma2(d1, w2.y, a1[o4*2+1]);
        }
    }
    int lane = tid & 31;
    #pragma unroll
    for (int o2 = 0; o2 < 16; o2++) {
        float pe0, po0, pe1, po1;
        upk(a0[o2], pe0, po0);
        upk(a1[o2], pe1, po1);
        int oA = o2*2, oB = o2*2 + 1;
        float2 sv; sv.x = pe0; sv.y = pe1;
        *(float2*)&g_Y[(base + (unsigned)oA * Sd) & MH] = sv;
        float2 tv; tv.x = po0; tv.y = po1;
        *(float2*)&g_Y[(base + (unsigned)oB * Sd) & MH] = tv;
        float rA = pe0 + pe1, qA = pe0*pe0 + pe1*pe1;
        float rB = po0 + po1, qB = po0*po0 + po1*po1;
        #pragma unroll
        for (int ofs = 16; ofs; ofs >>= 1) {
            rA += __shfl_down_sync(0xffffffffu, rA, ofs);
            qA += __shfl_down_sync(0xffffffffu, qA, ofs);
            rB += __shfl_down_sync(0xffffffffu, rB, ofs);
            qB += __shfl_down_sync(0xffffffffu, qB, ofs);
        }
        if (lane == 0) {
            atomicAdd(&s1[oA], rA); atomicAdd(&s2[oA], qA);
            atomicAdd(&s1[oB], rB); atomicAdd(&s2[oB], qB);
        }
    }
    __syncthreads();
    if (tid < 32) {
        int n = nbk >> 1;
        atomicAdd(&g_acc[((n*32 + tid)*2 + 0) & 127], (double)s1[tid]);
        atomicAdd(&g_acc[((n*32 + tid)*2 + 1) & 127], (double)s2[tid]);
    }
}

// Forward Z, 2 x-tiles packed as f32x2 lanes (ONLY change vs best). grid (32,128), block 512
__global__ void specz_k() {
    __shared__ __align__(16) ull tileP[64*66];
    __shared__ __align__(16) ull twcP[512], twsP[512];
    int tid = threadIdx.x;
    int x0 = blockIdx.x * 2, f = blockIdx.y;
    {   int kz = tid >> 6, z = tid & 63;
        float sv, cv; sincospif(-(float)(kz*z) * (1.0f/32.0f), &sv, &cv);
        twcP[tid] = pk(cv, cv); twsP[tid] = pk(sv, sv); }
    unsigned sb0 = (unsigned)f * Sd + (unsigned)x0 * 4096u;
    unsigned sb1 = sb0 + 4096u;
    #pragma unroll
    for (int i = 0; i < 2; i++) {
        int j = tid + i*512;
        int y = j >> 4, z0 = (j & 15)*4;
        float4 a = *(const float4*)&g_H[(sb0 + (unsigned)j*4u) & MH];
        float4 b = *(const float4*)&g_H[(sb1 + (unsigned)j*4u) & MH];
        ulonglong2 p0, p1;
        p0.x = pk(a.x, b.x); p0.y = pk(a.y, b.y);
        p1.x = pk(a.z, b.z); p1.y = pk(a.w, b.w);
        *(ulonglong2*)&tileP[y*66 + z0]     = p0;
        *(ulonglong2*)&tileP[y*66 + z0 + 2] = p1;
    }
    __syncthreads();
    int kz = tid >> 6, y = tid & 63;
    ull accR = pk(0.f, 0.f), accI = accR;
    #pragma unroll
    for (int z4 = 0; z4 < 16; z4++) {
        ulonglong2 d0 = *(const ulonglong2*)&tileP[y*66 + z4*4];
        ulonglong2 d1 = *(const ulonglong2*)&tileP[y*66 + z4*4 + 2];
        ulonglong2 c0 = *(const ulonglong2*)&twcP[kz*64 + z4*4];
        ulonglong2 c1 = *(const ulonglong2*)&twcP[kz*64 + z4*4 + 2];
        ulonglong2 s0 = *(const ulonglong2*)&twsP[kz*64 + z4*4];
        ulonglong2 s1 = *(const ulonglong2*)&twsP[kz*64 + z4*4 + 2];
        accR = fma2(d0.x, c0.x, accR); accI = fma2(d0.x, s0.x, accI);
        accR = fma2(d0.y, c0.y, accR); accI = fma2(d0.y, s0.y, accI);
        accR = fma2(d1.x, c1.x, accR); accI = fma2(d1.x, s1.x, accI);
        accR = fma2(d1.y, c1.y, accR); accI = fma2(d1.y, s1.y, accI);
    }
    float re0, re1, im0, im1;
    upk(accR, re0, re1); upk(accI, im0, im1);
    unsigned o0 = ((unsigned)(f*64 + x0)*8u + kz)*128u + y;
    g_FZ[o0 & MFZ] = re0; g_FZ[(o0 + 64) & MFZ] = im0;
    unsigned o1 = ((unsigned)(f*64 + x0 + 1)*8u + kz)*128u + y;
    g_FZ[o1 & MFZ] = re1; g_FZ[(o1 + 64) & MFZ] = im1;
}

// Forward Y, ky-blocked (4 ky/thread) + FFMA2. grid (8,128), block 256
__global__ void specy_k() {
    __shared__ float sre[64*65], sim[64*65];
    __shared__ __align__(16) ulonglong2 twq[1024];
    int tid = threadIdx.x;
    int kz = blockIdx.x, f = blockIdx.y;
    for (int i = tid; i < 1024; i += 256) {
        int ky = i >> 6, y = i & 63;
        int kact = (ky < 8) ? ky : ky - 16;
        float sv, cv; sincospif(-(float)(kact*y) * (1.0f/32.0f), &sv, &cv);
        ulonglong2 q; q.x = pk(cv, sv); q.y = pk(-sv, cv);
        twq[i] = q;
    }
    unsigned base = (unsigned)f * 65536u + (unsigned)kz * 128u;
    #pragma unroll
    for (int i = 0; i < 8; i++) {
        int j = tid + i*256;
        int xx = j >> 5, rq = j & 31;
        int r0 = rq * 4;
        float4 vv = *(const float4*)&g_FZ[(base + (unsigned)xx*1024u + r0) & MFZ];
        int y0 = r0 & 63;
        float* dst = (r0 < 64) ? sre : sim;
        dst[xx*65 + y0 + 0] = vv.x; dst[xx*65 + y0 + 1] = vv.y;
        dst[xx*65 + y0 + 2] = vv.z; dst[xx*65 + y0 + 3] = vv.w;
    }
    __syncthreads();
    int kyg = tid >> 6, x = tid & 63;
    ull acc0 = pk(0.f,0.f), acc1 = acc0, acc2 = acc0, acc3 = acc0;
    #pragma unroll 8
    for (int y = 0; y < 64; y++) {
        float a = sre[x*65 + y], b = sim[x*65 + y];
        ull da = pk(a, a), db = pk(b, b);
        ulonglong2 t0 = twq[(kyg*4+0)*64 + y];
        ulonglong2 t1 = twq[(kyg*4+1)*64 + y];
        ulonglong2 t2 = twq[(kyg*4+2)*64 + y];
        ulonglong2 t3 = twq[(kyg*4+3)*64 + y];
        acc0 = fma2(da, t0.x, acc0); acc0 = fma2(db, t0.y, acc0);
        acc1 = fma2(da, t1.x, acc1); acc1 = fma2(db, t1.y, acc1);
        acc2 = fma2(da, t2.x, acc2); acc2 = fma2(db, t2.y, acc2);
        acc3 = fma2(da, t3.x, acc3); acc3 = fma2(db, t3.y, acc3);
    }
    #pragma unroll
    for (int q = 0; q < 4; q++) {
        ull a = (q==0)?acc0:(q==1)?acc1:(q==2)?acc2:acc3;
        float re, im; upk(a, re, im);
        int ky = kyg*4 + q;
        unsigned o = ((unsigned)(f*16 + ky)*8u + kz)*128u + x;
        g_FYZ[o & MFYZ] = re; g_FYZ[(o + 64) & MFYZ] = im;
    }
}

// Forward X. grid (16,128), block 128
__global__ void specx_k() {
    __shared__ float sh[1024];
    __shared__ float2 tw[1024];
    int tid = threadIdx.x;
    int ky = blockIdx.x, f = blockIdx.y;
    for (int idx = tid; idx < 1024; idx += 128) {
        int kxi = idx >> 6, xx = idx & 63;
        int kact = (kxi < 8) ? kxi : kxi - 16;
        float sv, cv; sincospif(-(float)(kact*xx) * (1.0f/32.0f), &sv, &cv);
        tw[idx].x = cv; tw[idx].y = sv;
        sh[idx] = g_FYZ[((unsigned)(f*16 + ky)*1024u + idx) & MFYZ];
    }
    __syncthreads();
    int kz = tid >> 4, kxi = tid & 15;
    float re = 0.f, im = 0.f;
    #pragma unroll 8
    for (int x = 0; x < 64; x++) {
        float a = sh[kz*128 + x], b = sh[kz*128 + 64 + x];
        float2 t = tw[kxi*64 + x];
        re += a*t.x - b*t.y;
        im += a*t.y + b*t.x;
    }
    int nb = f >> 5, ch = f & 31;
    int mode = (kxi*16 + ky)*8 + kz;
    unsigned o = ((unsigned)(nb*2048 + mode)*32u + ch)*2u;
    g_XF[o & MXF] = re; g_XF[(o + 1) & MXF] = im;
}

// Coalesced transpose-pack of REAL weights -> WP[n][mode][i][o]. grid 1024, block 256
__global__ void pack_t_r_k(const float* __restrict__ sw, long nsw) {
    __shared__ float st[32*129];
    int tid = threadIdx.x;
    int bid = blockIdx.x;
    int q = bid >> 8, i = (bid >> 3) & 31, m1 = bid & 7;
    const float scale = 1.0f / 262144.0f;
    long baseS = (long)(q*32 + i)*32768 + m1*128;
    for (int idx = tid; idx < 4096; idx += 256) {
        int o = idx >> 7, j = idx & 127;
        st[o*129 + j] = ldc(sw, baseS + (long)o*1024 + j, nsw) * scale;
    }
    __syncthreads();
    int kxi = m1 + (q & 1)*8;
    int kyb = (q >> 1)*8;
    unsigned baseT = (unsigned)kxi*131072u + (unsigned)i*32u;
    for (int idx = tid; idx < 4096; idx += 256) {
        int n = idx >> 11, m2 = (idx >> 8) & 7, m3 = (idx >> 5) & 7, o = idx & 31;
        unsigned T = (unsigned)n*2097152u + baseT + (unsigned)(kyb + m2)*8192u + (unsigned)m3*1024u + o;
        g_WP[T & MFZ] = st[o*129 + m2*16 + m3*2 + n];
    }
}

// Pack interleaved complex weights (fallback)
__global__ void pack_k(const float* __restrict__ sw, long nsw) {
    int idx = blockIdx.x * 256 + threadIdx.x;
    int o = idx & 31, i = (idx >> 5) & 31, mode = (idx >> 10) & 2047, n = idx >> 21;
    int kz = mode & 7, ky = (mode >> 3) & 15, kxi = mode >> 7;
    int q = (kxi >= 8 ? 1 : 0) + (ky >= 8 ? 2 : 0);
    int m1 = kxi & 7, m2 = ky & 7, m3 = kz;
    long src = ((((((long)q*32 + i)*32 + o)*8 + m1)*8 + m2)*8 + m3)*2 + n;
    const float scale = 1.0f / 262144.0f;
    g_WP[((unsigned)idx*2u) & MFZ]     = ldc(sw, src*2,     nsw) * scale;
    g_WP[((unsigned)idx*2u + 1) & MFZ] = ldc(sw, src*2 + 1, nsw) * scale;
}

// Pack split re/im planes (fallback)
__global__ void pack2_k(const float* __restrict__ swr, long nr,
                        const float* __restrict__ swi, long ni) {
    int idx = blockIdx.x * 256 + threadIdx.x;
    int o = idx & 31, i = (idx >> 5) & 31, mode = (idx >> 10) & 2047, n = idx >> 21;
    int kz = mode & 7, ky = (mode >> 3) & 15, kxi = mode >> 7;
    int q = (kxi >= 8 ? 1 : 0) + (ky >= 8 ? 2 : 0);
    int m1 = kxi & 7, m2 = ky & 7, m3 = kz;
    long src = ((((((long)q*32 + i)*32 + o)*8 + m1)*8 + m2)*8 + m3)*2 + n;
    const float scale = 1.0f / 262144.0f;
    g_WP[((unsigned)idx*2u) & MFZ]     = ldc(swr, src, nr) * scale;
    g_WP[((unsigned)idx*2u + 1) & MFZ] = ldc(swi, src, ni) * scale;
}

// Mode multiply, REAL weights + FFMA2. grid (2048,2), block 64
__global__ void modemul_r_k() {
    __shared__ __align__(16) float wsh[1024];
    __shared__ __align__(16) float xs[128];
    int tid = threadIdx.x;
    int mode = blockIdx.x, n = blockIdx.y;
    unsigned wslab = (unsigned)(n*2048 + mode) * 1024u;
    for (int i = tid; i < 1024; i += 64) wsh[i] = g_WP[(wslab + i) & MFZ];
    for (int idx = tid; idx < 128; idx += 64) {
        int b = idx >> 6, r = idx & 63;
        xs[idx] = g_XF[((unsigned)((n*2 + b)*2048 + mode)*64u + r) & MXF];
    }
    __syncthreads();
    int o = tid & 31, b = tid >> 5;
    const float* xv = xs + b*64;
    ull acc = pk(0.f, 0.f);
    #pragma unroll
    for (int i = 0; i < 32; i++) {
        float w = wsh[i*32 + o];
        ull x2 = *(const ull*)&xv[i*2];
        acc = fma2(x2, pk(w, w), acc);
    }
    float orr, oii; upk(acc, orr, oii);
    int kz = mode & 7, ky = (mode >> 3) & 15, kxi = mode >> 7;
    int nb = n*2 + b;
    unsigned addr = (((unsigned)(nb*32 + o)*8u + kz)*16u + ky)*32u + kxi;
    g_XO[addr & MXF] = orr;
    g_XO[(addr + 16) & MXF] = oii;
}

// Mode multiply, complex (fallback)
__global__ void modemul_k() {
    __shared__ float xs[128];
    __shared__ float2 wsh[1024];
    int tid = threadIdx.x;
    int mode = blockIdx.x, n = blockIdx.y;
    unsigned wslab = (unsigned)(n*2048 + mode) * 2048u;
    for (int i = tid; i < 1024; i += 64) {
        float2 wv;
        wv.x = g_WP[(wslab + (unsigned)i*2u) & MFZ];
        wv.y = g_WP[(wslab + (unsigned)i*2u + 1) & MFZ];
        wsh[i] = wv;
    }
    for (int idx = tid; idx < 128; idx += 64) {
        int b = idx >> 6, r = idx & 63;
        xs[idx] = g_XF[((unsigned)((n*2 + b)*2048 + mode)*64u + r) & MXF];
    }
    __syncthreads();
    int o = tid & 31, b = tid >> 5;
    const float* xv = xs + b*64;
    float orr = 0.f, oii = 0.f;
    #pragma unroll
    for (int i = 0; i < 32; i++) {
        float2 wv = wsh[i*32 + o];
        float xr = xv[i*2], xi = xv[i*2 + 1];
        orr += xr*wv.x - xi*wv.y;
        oii += xr*wv.y + xi*wv.x;
    }
    int kz = mode & 7, ky = (mode >> 3) & 15, kxi = mode >> 7;
    int nb = n*2 + b;
    unsigned addr = (((unsigned)(nb*32 + o)*8u + kz)*16u + ky)*32u + kxi;
    g_XO[addr & MXF] = orr;
    g_XO[(addr + 16) & MXF] = oii;
}

// Inverse X. grid (8,128), block 1024
__global__ __launch_bounds__(1024) void invx_k() {
    __shared__ float xsh[16*33];
    __shared__ float2 tw[1024];
    int tid = threadIdx.x;
    int kz = blockIdx.x, f2 = blockIdx.y;
    {   int x = tid >> 4, kxi = tid & 15;
        int kact = (kxi < 8) ? kxi : kxi - 16;
        float sv, cv; sincospif((float)(kact*x) * (1.0f/32.0f), &sv, &cv);
        tw[x*16 + kxi].x = cv; tw[x*16 + kxi].y = sv; }
    if (tid < 512) {
        int ky = tid >> 5, r = tid & 31;
        xsh[ky*33 + r] = g_XO[((unsigned)(f2*8 + kz)*512u + tid) & MXF];
    }
    __syncthreads();
    int x = tid >> 4, ky = tid & 15;
    float re = 0.f, im = 0.f;
    #pragma unroll
    for (int k = 0; k < 16; k++) {
        float a = xsh[ky*33 + k], b = xsh[ky*33 + 16 + k];
        float2 t = tw[x*16 + k];
        re += a*t.x - b*t.y;
        im += a*t.y + b*t.x;
    }
    unsigned o = ((unsigned)(f2*64 + x)*8u + kz)*32u + ky;
    g_GX[o & MFYZ] = re; g_GX[(o + 16) & MFYZ] = im;
}

// FUSED inverse Y + inverse Z + BN + residual + ReLU, FFMA2 invz. grid (64,128), block 512
__global__ void invyz_k(const float* __restrict__ gamma, long ng,
                        const float* __restrict__ beta, long nbt) {
    __shared__ float gsh[8*34];
    __shared__ float2 ty1[1024];
    __shared__ ull tileRe[64*9], tileIm[64*9];
    __shared__ ull tzc[8*33], tzs[8*33];
    __shared__ float sh_mean, sh_inv, sh_g, sh_b;
    int tid = threadIdx.x;
    int x = blockIdx.x, f2 = blockIdx.y;
    #pragma unroll
    for (int i = 0; i < 2; i++) {
        int idx = tid + i*512;
        int y = idx >> 4, ky = idx & 15;
        int kact = (ky < 8) ? ky : ky - 16;
        float sv, cv; sincospif((float)(kact*y) * (1.0f/32.0f), &sv, &cv);
        ty1[idx].x = cv; ty1[idx].y = sv;
    }
    if (tid < 256) {
        int k = tid >> 5, zp = tid & 31;
        int z0 = zp*2, z1 = z0 + 1;
        float s0, c0, s1v, c1v;
        sincospif((float)(k*z0) * (1.0f/32.0f), &s0, &c0);
        sincospif((float)(k*z1) * (1.0f/32.0f), &s1v, &c1v);
        tzc[k*33 + zp] = pk(2.0f*c0, 2.0f*c1v);
        tzs[k*33 + zp] = pk(-2.0f*s0, -2.0f*s1v);
    }
    if (tid < 256) {
        int kz = tid >> 5, r = tid & 31;
        int reim = r >> 4, ky = r & 15;
        gsh[kz*34 + reim*17 + ky] = g_GX[((unsigned)(f2*64 + x)*256u + tid) & MFYZ];
    }
    if (tid == 0) {
        int n = f2 >> 6, o = f2 & 31;
        double s1 = g_acc[((n*32 + o)*2) & 127], s2 = g_acc[((n*32 + o)*2 + 1) & 127];
        float mean = (float)(s1 * (1.0/BN_CNT));
        float var  = (float)(s2 * (1.0/BN_CNT)) - mean*mean;
        sh_mean = mean;
        sh_inv = rsqrtf(var + 1e-5f);
        sh_g = (o < ng)  ? gamma[o] : 1.0f;
        sh_b = (o < nbt) ? beta[o]  : 0.0f;
    }
    __syncthreads();
    {
        int y = tid >> 3, kz = tid & 7;
        float re = 0.f, im = 0.f;
        #pragma unroll
        for (int ky = 0; ky < 16; ky++) {
            float a = gsh[kz*34 + ky], b = gsh[kz*34 + 17 + ky];
            float2 t = ty1[y*16 + ky];
            re += a*t.x - b*t.y;
            im += a*t.y + b*t.x;
        }
        tileRe[y*9 + kz] = pk(re, re);
        tileIm[y*9 + kz] = pk(im, im);
    }
    __syncthreads();
    float mean = sh_mean, inv = sh_inv, gm = sh_g, bt = sh_b;
    int y = tid >> 3, zg = tid & 7;
    ull vp0, vp1, vp2, vp3;
    vp0 = vp1 = vp2 = vp3 = tileRe[y*9 + 0];
    int zpb = zg*4;
    #pragma unroll
    for (int k = 1; k < 8; k++) {
        ull A = tileRe[y*9 + k], B = tileIm[y*9 + k];
        vp0 = fma2(A, tzc[k*33 + zpb+0], vp0); vp0 = fma2(B, tzs[k*33 + zpb+0], vp0);
        vp1 = fma2(A, tzc[k*33 + zpb+1], vp1); vp1 = fma2(B, tzs[k*33 + zpb+1], vp1);
        vp2 = fma2(A, tzc[k*33 + zpb+2], vp2); vp2 = fma2(B, tzs[k*33 + zpb+2], vp2);
        vp3 = fma2(A, tzc[k*33 + zpb+3], vp3); vp3 = fma2(B, tzs[k*33 + zpb+3], vp3);
    }
    float vz[8];
    upk(vp0, vz[0], vz[1]); upk(vp1, vz[2], vz[3]);
    upk(vp2, vz[4], vz[5]); upk(vp3, vz[6], vz[7]);
    unsigned base = (unsigned)f2 * Sd + (unsigned)(x*4096 + y*64 + zg*8);
    float4 y0 = *(const float4*)&g_Y[base & MH];
    float4 y1 = *(const float4*)&g_Y[(base + 4) & MH];
    float4 o0, o1;
    o0.x = fmaxf(vz[0] + gm*(y0.x - mean)*inv + bt, 0.f);
    o0.y = fmaxf(vz[1] + gm*(y0.y - mean)*inv + bt, 0.f);
    o0.z = fmaxf(vz[2] + gm*(y0.z - mean)*inv + bt, 0.f);
    o0.w = fmaxf(vz[3] + gm*(y0.w - mean)*inv + bt, 0.f);
    o1.x = fmaxf(vz[4] + gm*(y1.x - mean)*inv + bt, 0.f);
    o1.y = fmaxf(vz[5] + gm*(y1.y - mean)*inv + bt, 0.f);
    o1.z = fmaxf(vz[6] + gm*(y1.z - mean)*inv + bt, 0.f);
    o1.w = fmaxf(vz[7] + gm*(y1.w - mean)*inv + bt, 0.f);
    *(float4*)&g_H[base & MH] = o0;
    *(float4*)&g_H[(base + 4) & MH] = o1;
}

// fc1(relu)+fc2 head, 2 points/thread, j16-block FFMA2
__global__ void fc12_k(const float* __restrict__ w1, long nw1,
                       const float* __restrict__ b1, long nb1,
                       const float* __restrict__ w2, long nw2,
                       const float* __restrict__ b2, long nb2,
                       float* __restrict__ out, int nOut) {
    __shared__ __align__(16) float w1s[4096];
    __shared__ __align__(16) float b1s[128];
    __shared__ __align__(16) float w2s[128];
    int tid = threadIdx.x;
    for (int i = tid; i < 4096; i += 256) w1s[i] = ldc(w1, i, nw1);
    if (tid < 128) { b1s[tid] = ldc(b1, tid, nb1); w2s[tid] = ldc(w2, tid, nw2); }
    __syncthreads();
    int t = blockIdx.x * 256 + tid;
    int p0 = t * 2;
    if (p0 >= nOut) return;
    int s = t & (Sd - 1), b = (t >> 18) & 1;
    unsigned base0 = (unsigned)((0*2 + b)*32) * Sd + (unsigned)s;
    unsigned base1 = (unsigned)((1*2 + b)*32) * Sd + (unsigned)s;
    float v0[32], v1[32];
    #pragma unroll
    for (int c = 0; c < 32; c++) {
        v0[c] = g_H[(base0 + (unsigned)c * Sd) & MH];
        v1[c] = g_H[(base1 + (unsigned)c * Sd) & MH];
    }
    float bias2 = (nb2 > 0) ? b2[0] : 0.0f;
    float acc0 = bias2, acc1 = bias2;
    #pragma unroll
    for (int jb = 0; jb < 8; jb++) {
        ull hp0[8], hp1[8];
        #pragma unroll
        for (int q = 0; q < 8; q++) {
            ull bq = *(const ull*)&b1s[jb*16 + q*2];
            hp0[q] = bq; hp1[q] = bq;
        }
        #pragma unroll
        for (int c = 0; c < 32; c++) {
            ull d0 = pk(v0[c], v0[c]), d1 = pk(v1[c], v1[c]);
            const ull* wrow = (const ull*)&w1s[c*128 + jb*16];
            #pragma unroll
            for (int q = 0; q < 8; q++) {
                ull wq = wrow[q];
                hp0[q] = fma2(d0, wq, hp0[q]);
                hp1[q] = fma2(d1, wq, hp1[q]);
            }
        }
        #pragma unroll
        for (int q = 0; q < 8; q++) {
            float h0a, h0b, h1a, h1b;
            upk(hp0[q], h0a, h0b);
            upk(hp1[q], h1a, h1b);
            float2 wv = *(const float2*)&w2s[jb*16 + q*2];
            acc0 += fmaxf(h0a, 0.f)*wv.x + fmaxf(h0b, 0.f)*wv.y;
            acc1 += fmaxf(h1a, 0.f)*wv.x + fmaxf(h1b, 0.f)*wv.y;
        }
    }
    out[p0] = acc0;
    if (p0 + 1 < nOut) out[p0 + 1] = acc1;
}

// ---------------- launch ----------------
extern "C" void kernel_launch(void* const* d_in, const int* in_sizes, int n_in,
                              void* d_out, int out_size) {
    bool bytesMode = false, sawElem = false;
    for (int i = 0; i < n_in; i++) {
        if (in_sizes[i] == 416)  sawElem = true;
        if (in_sizes[i] == 1664) bytesMode = true;
    }
    if (sawElem) bytesMode = false;

    long esz[64];
    int ncap = n_in < 64 ? n_in : 64;
    for (int i = 0; i < ncap; i++) {
        long s = (long)in_sizes[i];
        esz[i] = bytesMode ? s / 4 : s;
    }

    int idxX = -1, idxF0W = -1, idxF1W = -1, idxF2B = -1;
    int big[8]; int nbig = 0;
    int cw[4];  int ncw = 0;
    int s128[4]; int n128 = 0;
    int s32[12]; int n32 = 0;
    for (int i = 0; i < ncap; i++) {
        long s = esz[i];
        if (s > 10000000)      idxX = i;
        else if (s >= 2000000) { if (nbig < 8) big[nbig++] = i; }
        else if (s == 4096)    idxF1W = i;
        else if (s == 1024)    { if (ncw < 4) cw[ncw++] = i; }
        else if (s == 416)     idxF0W = i;
        else if (s == 128)     { if (n128 < 4) s128[n128++] = i; }
        else if (s == 32)      { if (n32 < 12) s32[n32++] = i; }
        else if (s == 1)       idxF2B = i;
    }

    bool ok = (idxX >= 0) && (idxF0W >= 0) && (idxF1W >= 0) && (idxF2B >= 0)
              && (nbig == 3 || nbig == 6) && (ncw >= 3) && (n128 >= 2) && (n32 >= 10);

    int iX, iF0W, iF0B, iSWa[3], iSWb[3], iCW[3], iCB[3], iG[3], iB[3], iF1W, iF1B, iF2W, iF2B;
    bool swSplit = false;

    if (!ok) {
        int cap = (n_in > 0) ? n_in - 1 : 0;
        #define CLP(v) ((v) > cap ? cap : (v))
        iX = CLP(0); iF0W = CLP(1); iF0B = CLP(2);
        iSWa[0] = CLP(3); iSWa[1] = CLP(4); iSWa[2] = CLP(5);
        iSWb[0] = iSWb[1] = iSWb[2] = CLP(3);
        iCW[0] = CLP(6); iCB[0] = CLP(7); iCW[1] = CLP(8); iCB[1] = CLP(9);
        iCW[2] = CLP(10); iCB[2] = CLP(11);
        iG[0] = CLP(12); iB[0] = CLP(13); iG[1] = CLP(14); iB[1] = CLP(15);
        iG[2] = CLP(16); iB[2] = CLP(17);
        iF1W = CLP(18); iF1B = CLP(19); iF2W = CLP(20); iF2B = CLP(21);
        #undef CLP
    } else {
        iX = idxX; iF0W = idxF0W; iF1W = idxF1W; iF2B = idxF2B;
        iF1B = s128[0]; iF2W = s128[1];
        iCW[0] = cw[0]; iCW[1] = cw[1]; iCW[2] = cw[2];
        bool sigOrder = (idxX == 0);
        if (sigOrder) {
            iF0B = s32[0];
            iCB[0] = s32[1]; iCB[1] = s32[2]; iCB[2] = s32[3];
            iG[0] = s32[4]; iB[0] = s32[5];
            iG[1] = s32[6]; iB[1] = s32[7];
            iG[2] = s32[8]; iB[2] = s32[9];
        } else {
            iB[0] = s32[0]; iB[1] = s32[1]; iB[2] = s32[2];
            iCB[0] = s32[3]; iCB[1] = s32[4]; iCB[2] = s32[5];
            iF0B = s32[6];
            iG[0] = s32[7]; iG[1] = s32[8]; iG[2] = s32[9];
        }
        swSplit = (nbig == 6);
        if (swSplit) {
            for (int k = 0; k < 3; k++) {
                if (sigOrder) { iSWa[k] = big[2*k]; iSWb[k] = big[2*k + 1]; }
                else          { iSWb[k] = big[2*k]; iSWa[k] = big[2*k + 1]; }
            }
        } else {
            for (int k = 0; k < 3; k++) { iSWa[k] = big[k]; iSWb[k] = big[k]; }
        }
    }

    #define PTR(i) ((const float*)d_in[i])
    #define ESZ(i) (esz[i])

    for (int k = 0; k < 3; k++) {
        bool realW = !swSplit && (ESZ(iSWa[k]) < 8000000);
        zero_acc_k<<<1, 128>>>();
        if (k == 0)
            fc0conv_k<<<2048, 256>>>(PTR(iX), ESZ(iX), PTR(iF0W), ESZ(iF0W),
                                     PTR(iF0B), ESZ(iF0B),
                                     PTR(iCW[0]), ESZ(iCW[0]), PTR(iCB[0]), ESZ(iCB[0]));
        else
            convB_k<<<dim3(512, 4), 256>>>(PTR(iCW[k]), ESZ(iCW[k]), PTR(iCB[k]), ESZ(iCB[k]));
        specz_k<<<dim3(32, 128), 512>>>();
        specy_k<<<dim3(8, 128), 256>>>();
        specx_k<<<dim3(16, 128), 128>>>();
        if (swSplit)       pack2_k<<<16384, 256>>>(PTR(iSWa[k]), ESZ(iSWa[k]), PTR(iSWb[k]), ESZ(iSWb[k]));
        else if (!realW)   pack_k<<<16384, 256>>>(PTR(iSWa[k]), ESZ(iSWa[k]));
        else               pack_t_r_k<<<1024, 256>>>(PTR(iSWa[k]), ESZ(iSWa[k]));
        if (realW) modemul_r_k<<<dim3(2048, 2), 64>>>();
        else       modemul_k<<<dim3(2048, 2), 64>>>();
        invx_k<<<dim3(8, 128), 1024>>>();
        invyz_k<<<dim3(64, 128), 512>>>(PTR(iG[k]), ESZ(iG[k]), PTR(iB[k]), ESZ(iB[k]));
    }

    long nOutL = (long)out_size;
    if (nOutL > 1048576) nOutL = 1048576;
    int nOut = (int)nOutL;
    if (nOut > 0)
        fc12_k<<<(nOut/2 + 255) / 256, 256>>>(PTR(iF1W), ESZ(iF1W), PTR(iF1B), ESZ(iF1B),
                                              PTR(iF2W), ESZ(iF2W), PTR(iF2B), ESZ(iF2B),
                                              (float*)d_out, nOut);
    #undef PTR
    #undef ESZ
}

// round 17
// speedup vs baseline: 1.6508x; 1.6508x over previous
#include <cuda_runtime.h>
#include <math.h>

#define Sd 262144
#define BN_CNT 524288.0

#define MH   0x1FFFFFFu
#define MFZ  0x7FFFFFu
#define MFYZ 0x1FFFFFu
#define MXF  0x7FFFFu

typedef unsigned long long ull;

__device__ __align__(16) float g_H [1u<<25];
__device__ __align__(16) float g_Y [1u<<25];
__device__ __align__(16) float g_FZ [1u<<23];
__device__ __align__(16) float g_FYZ[1u<<21];
__device__ __align__(16) float g_XF [1u<<19];
__device__ __align__(16) float g_XO [1u<<19];
__device__ __align__(16) float g_GX [1u<<21];
__device__ __align__(16) float g_WP [1u<<23];
__device__ double g_acc[128];

__device__ __forceinline__ float ldc(const float* p, long i, long n) {
    return (i >= 0 && i < n) ? p[i] : 0.0f;
}
__device__ __forceinline__ ull pk(float x, float y) {
    ull r; asm("mov.b64 %0, {%1,%2};" : "=l"(r) : "f"(x), "f"(y)); return r;
}
__device__ __forceinline__ void upk(ull v, float& x, float& y) {
    asm("mov.b64 {%0,%1}, %2;" : "=f"(x), "=f"(y) : "l"(v));
}
__device__ __forceinline__ ull fma2(ull a, ull b, ull c) {
    ull d; asm("fma.rn.f32x2 %0, %1, %2, %3;" : "=l"(d) : "l"(a), "l"(b), "l"(c)); return d;
}

__global__ void zero_acc_k() { g_acc[threadIdx.x & 127] = 0.0; }

// fused fc0 + conv1x1(block0) + BN stats. grid 2048, block 256
__global__ void fc0conv_k(const float* __restrict__ xin, long nx,
                          const float* __restrict__ w, long nw,
                          const float* __restrict__ bias, long nb,
                          const float* __restrict__ cw, long ncwn,
                          const float* __restrict__ cb, long ncb) {
    __shared__ __align__(16) float wt[512];
    __shared__ __align__(16) float cws[1024];
    __shared__ float bs[32], cbs[32], s1[64], s2[64];
    int tid = threadIdx.x;
    for (int i = tid; i < 512; i += 256) {
        int o = i >> 4, ii = i & 15;
        wt[i] = (ii < 13) ? ldc(w, ii*32 + o, nw) : 0.0f;
    }
    for (int i = tid; i < 1024; i += 256) cws[i] = ldc(cw, i, ncwn);
    if (tid < 32) { bs[tid] = ldc(bias, tid, nb); cbs[tid] = ldc(cb, tid, ncb); }
    if (tid < 64) { s1[tid] = 0.f; s2[tid] = 0.f; }
    __syncthreads();
    int p = blockIdx.x * 256 + tid;
    int b = (p >> 18) & 1, s = p & (Sd - 1);
    long off = (long)p * 26;
    float h0[32], h1[32];
    {
        float v0[13], v1[13];
        #pragma unroll
        for (int i = 0; i < 13; i++) { v0[i] = ldc(xin, off + i, nx); v1[i] = ldc(xin, off + 13 + i, nx); }
        #pragma unroll
        for (int o = 0; o < 32; o++) {
            float a0 = bs[o], a1 = bs[o];
            #pragma unroll
            for (int i4 = 0; i4 < 3; i4++) {
                float4 wv = *(const float4*)&wt[o*16 + i4*4];
                a0 += v0[i4*4+0]*wv.x + v0[i4*4+1]*wv.y + v0[i4*4+2]*wv.z + v0[i4*4+3]*wv.w;
                a1 += v1[i4*4+0]*wv.x + v1[i4*4+1]*wv.y + v1[i4*4+2]*wv.z + v1[i4*4+3]*wv.w;
            }
            a0 += v0[12]*wt[o*16+12];
            a1 += v1[12]*wt[o*16+12];
            h0[o] = a0; h1[o] = a1;
            g_H[((unsigned)((0*2 + b)*32 + o)*Sd + s) & MH] = a0;
            g_H[((unsigned)((1*2 + b)*32 + o)*Sd + s) & MH] = a1;
        }
    }
    int lane = tid & 31;
    #pragma unroll
    for (int o = 0; o < 32; o++) {
        float y0 = cbs[o], y1 = cbs[o];
        #pragma unroll
        for (int c4 = 0; c4 < 8; c4++) {
            float4 wv = *(const float4*)&cws[o*32 + c4*4];
            y0 += h0[c4*4+0]*wv.x + h0[c4*4+1]*wv.y + h0[c4*4+2]*wv.z + h0[c4*4+3]*wv.w;
            y1 += h1[c4*4+0]*wv.x + h1[c4*4+1]*wv.y + h1[c4*4+2]*wv.z + h1[c4*4+3]*wv.w;
        }
        g_Y[((unsigned)((0*2 + b)*32 + o)*Sd + s) & MH] = y0;
        g_Y[((unsigned)((1*2 + b)*32 + o)*Sd + s) & MH] = y1;
        float r0 = y0, q0 = y0*y0, r1 = y1, q1 = y1*y1;
        #pragma unroll
        for (int ofs = 16; ofs; ofs >>= 1) {
            r0 += __shfl_down_sync(0xffffffffu, r0, ofs);
            q0 += __shfl_down_sync(0xffffffffu, q0, ofs);
            r1 += __shfl_down_sync(0xffffffffu, r1, ofs);
            q1 += __shfl_down_sync(0xffffffffu, q1, ofs);
        }
        if (lane == 0) {
            atomicAdd(&s1[o], r0); atomicAdd(&s2[o], q0);
            atomicAdd(&s1[32 + o], r1); atomicAdd(&s2[32 + o], q1);
        }
    }
    __syncthreads();
    if (tid < 64) {
        atomicAdd(&g_acc[(tid*2 + 0) & 127], (double)s1[tid]);
        atomicAdd(&g_acc[(tid*2 + 1) & 127], (double)s2[tid]);
    }
}

// 1x1 conv + BN stats, 2 points/thread, o-pair packed FFMA2. grid (512,4), block 256
__global__ void convB_k(const float* __restrict__ w, long nw,
                        const float* __restrict__ bias, long nb) {
    __shared__ __align__(16) float ws[1024];
    __shared__ __align__(16) ulonglong2 wq[256];
    __shared__ float bs[32], s1[32], s2[32];
    int tid = threadIdx.x;
    for (int i = tid; i < 1024; i += 256) ws[i] = ldc(w, i, nw);
    if (tid < 32) { bs[tid] = ldc(bias, tid, nb); s1[tid] = 0.f; s2[tid] = 0.f; }
    __syncthreads();
    {
        int o4 = tid >> 5, c = tid & 31;
        ulonglong2 q;
        q.x = pk(ws[(o4*4+0)*32 + c], ws[(o4*4+1)*32 + c]);
        q.y = pk(ws[(o4*4+2)*32 + c], ws[(o4*4+3)*32 + c]);
        wq[tid] = q;
    }
    __syncthreads();
    int nbk = blockIdx.y;
    int s0 = (blockIdx.x * 256 + tid) * 2;
    unsigned base = (unsigned)nbk * 32u * Sd + (unsigned)s0;
    ull a0[16], a1[16];
    #pragma unroll
    for (int o4 = 0; o4 < 8; o4++) {
        a0[o4*2]   = pk(bs[o4*4+0], bs[o4*4+1]);
        a0[o4*2+1] = pk(bs[o4*4+2], bs[o4*4+3]);
        a1[o4*2]   = a0[o4*2];
        a1[o4*2+1] = a0[o4*2+1];
    }
    #pragma unroll
    for (int c = 0; c < 32; c++) {
        ull vp = *(const ull*)&g_H[(base + (unsigned)c * Sd) & MH];
        float vx, vy; upk(vp, vx, vy);
        ull d0 = pk(vx, vx), d1 = pk(vy, vy);
        #pragma unroll
        for (int o4 = 0; o4 < 8; o4++) {
            ulonglong2 w2 = wq[o4*32 + c];
            a0[o4*2]   = fma2(d0, w2.x, a0[o4*2]);
            a0[o4*2+1] = fma2(d0, w2.y, a0[o4*2+1]);
            a1[o4*2]   = fma2(d1, w2.x, a1[o4*2]);
            a1[o4*2+1] = fma2(d1, w2.y, a1[o4*2+1]);
        }
    }
    int lane = tid & 31;
    #pragma unroll
    for (int o2 = 0; o2 < 16; o2++) {
        float pe0, po0, pe1, po1;
        upk(a0[o2], pe0, po0);
        upk(a1[o2], pe1, po1);
        int oA = o2*2, oB = o2*2 + 1;
        float2 sv; sv.x = pe0; sv.y = pe1;
        *(float2*)&g_Y[(base + (unsigned)oA * Sd) & MH] = sv;
        float2 tv; tv.x = po0; tv.y = po1;
        *(float2*)&g_Y[(base + (unsigned)oB * Sd) & MH] = tv;
        float rA = pe0 + pe1, qA = pe0*pe0 + pe1*pe1;
        float rB = po0 + po1, qB = po0*po0 + po1*po1;
        #pragma unroll
        for (int ofs = 16; ofs; ofs >>= 1) {
            rA += __shfl_down_sync(0xffffffffu, rA, ofs);
            qA += __shfl_down_sync(0xffffffffu, qA, ofs);
            rB += __shfl_down_sync(0xffffffffu, rB, ofs);
            qB += __shfl_down_sync(0xffffffffu, qB, ofs);
        }
        if (lane == 0) {
            atomicAdd(&s1[oA], rA); atomicAdd(&s2[oA], qA);
            atomicAdd(&s1[oB], rB); atomicAdd(&s2[oB], qB);
        }
    }
    __syncthreads();
    if (tid < 32) {
        int n = nbk >> 1;
        atomicAdd(&g_acc[((n*32 + tid)*2 + 0) & 127], (double)s1[tid]);
        atomicAdd(&g_acc[((n*32 + tid)*2 + 1) & 127], (double)s2[tid]);
    }
}

// Forward Z, 2 x-tiles per block. grid (32,128), block 512
__global__ void specz_k() {
    __shared__ __align__(16) float tile0[64*68];
    __shared__ __align__(16) float tile1[64*68];
    __shared__ __align__(16) float twc[512], tws[512];
    int tid = threadIdx.x;
    int x0 = blockIdx.x * 2, f = blockIdx.y;
    {   int kz = tid >> 6, z = tid & 63;
        float sv, cv; sincospif(-(float)(kz*z) * (1.0f/32.0f), &sv, &cv);
        twc[tid] = cv; tws[tid] = sv; }
    unsigned sb0 = (unsigned)f * Sd + (unsigned)x0 * 4096u;
    unsigned sb1 = sb0 + 4096u;
    #pragma unroll
    for (int i = 0; i < 2; i++) {
        int j = tid + i*512;
        int y = j >> 4, z0 = (j & 15)*4;
        *(float4*)&tile0[y*68 + z0] = *(const float4*)&g_H[(sb0 + (unsigned)j*4u) & MH];
        *(float4*)&tile1[y*68 + z0] = *(const float4*)&g_H[(sb1 + (unsigned)j*4u) & MH];
    }
    __syncthreads();
    int kz = tid >> 6, y = tid & 63;
    float re0 = 0.f, im0 = 0.f, re1 = 0.f, im1 = 0.f;
    #pragma unroll
    for (int z4 = 0; z4 < 16; z4++) {
        float4 cc = *(const float4*)&twc[kz*64 + z4*4];
        float4 ss = *(const float4*)&tws[kz*64 + z4*4];
        float4 a = *(const float4*)&tile0[y*68 + z4*4];
        float4 b = *(const float4*)&tile1[y*68 + z4*4];
        re0 += a.x*cc.x + a.y*cc.y + a.z*cc.z + a.w*cc.w;
        im0 += a.x*ss.x + a.y*ss.y + a.z*ss.z + a.w*ss.w;
        re1 += b.x*cc.x + b.y*cc.y + b.z*cc.z + b.w*cc.w;
        im1 += b.x*ss.x + b.y*ss.y + b.z*ss.z + b.w*ss.w;
    }
    unsigned o0 = ((unsigned)(f*64 + x0)*8u + kz)*128u + y;
    g_FZ[o0 & MFZ] = re0; g_FZ[(o0 + 64) & MFZ] = im0;
    unsigned o1 = ((unsigned)(f*64 + x0 + 1)*8u + kz)*128u + y;
    g_FZ[o1 & MFZ] = re1; g_FZ[(o1 + 64) & MFZ] = im1;
}

// Forward Y, ky-blocked (4 ky/thread) + FFMA2. grid (8,128), block 256
__global__ void specy_k() {
    __shared__ float sre[64*65], sim[64*65];
    __shared__ __align__(16) ulonglong2 twq[1024];
    int tid = threadIdx.x;
    int kz = blockIdx.x, f = blockIdx.y;
    for (int i = tid; i < 1024; i += 256) {
        int ky = i >> 6, y = i & 63;
        int kact = (ky < 8) ? ky : ky - 16;
        float sv, cv; sincospif(-(float)(kact*y) * (1.0f/32.0f), &sv, &cv);
        ulonglong2 q; q.x = pk(cv, sv); q.y = pk(-sv, cv);
        twq[i] = q;
    }
    unsigned base = (unsigned)f * 65536u + (unsigned)kz * 128u;
    #pragma unroll
    for (int i = 0; i < 8; i++) {
        int j = tid + i*256;
        int xx = j >> 5, rq = j & 31;
        int r0 = rq * 4;
        float4 vv = *(const float4*)&g_FZ[(base + (unsigned)xx*1024u + r0) & MFZ];
        int y0 = r0 & 63;
        float* dst = (r0 < 64) ? sre : sim;
        dst[xx*65 + y0 + 0] = vv.x; dst[xx*65 + y0 + 1] = vv.y;
        dst[xx*65 + y0 + 2] = vv.z; dst[xx*65 + y0 + 3] = vv.w;
    }
    __syncthreads();
    int kyg = tid >> 6, x = tid & 63;
    ull acc0 = pk(0.f,0.f), acc1 = acc0, acc2 = acc0, acc3 = acc0;
    #pragma unroll 8
    for (int y = 0; y < 64; y++) {
        float a = sre[x*65 + y], b = sim[x*65 + y];
        ull da = pk(a, a), db = pk(b, b);
        ulonglong2 t0 = twq[(kyg*4+0)*64 + y];
        ulonglong2 t1 = twq[(kyg*4+1)*64 + y];
        ulonglong2 t2 = twq[(kyg*4+2)*64 + y];
        ulonglong2 t3 = twq[(kyg*4+3)*64 + y];
        acc0 = fma2(da, t0.x, acc0); acc0 = fma2(db, t0.y, acc0);
        acc1 = fma2(da, t1.x, acc1); acc1 = fma2(db, t1.y, acc1);
        acc2 = fma2(da, t2.x, acc2); acc2 = fma2(db, t2.y, acc2);
        acc3 = fma2(da, t3.x, acc3); acc3 = fma2(db, t3.y, acc3);
    }
    #pragma unroll
    for (int q = 0; q < 4; q++) {
        ull a = (q==0)?acc0:(q==1)?acc1:(q==2)?acc2:acc3;
        float re, im; upk(a, re, im);
        int ky = kyg*4 + q;
        unsigned o = ((unsigned)(f*16 + ky)*8u + kz)*128u + x;
        g_FYZ[o & MFYZ] = re; g_FYZ[(o + 64) & MFYZ] = im;
    }
}

// Forward X. grid (16,128), block 128
__global__ void specx_k() {
    __shared__ float sh[1024];
    __shared__ float2 tw[1024];
    int tid = threadIdx.x;
    int ky = blockIdx.x, f = blockIdx.y;
    for (int idx = tid; idx < 1024; idx += 128) {
        int kxi = idx >> 6, xx = idx & 63;
        int kact = (kxi < 8) ? kxi : kxi - 16;
        float sv, cv; sincospif(-(float)(kact*xx) * (1.0f/32.0f), &sv, &cv);
        tw[idx].x = cv; tw[idx].y = sv;
        sh[idx] = g_FYZ[((unsigned)(f*16 + ky)*1024u + idx) & MFYZ];
    }
    __syncthreads();
    int kz = tid >> 4, kxi = tid & 15;
    float re = 0.f, im = 0.f;
    #pragma unroll 8
    for (int x = 0; x < 64; x++) {
        float a = sh[kz*128 + x], b = sh[kz*128 + 64 + x];
        float2 t = tw[kxi*64 + x];
        re += a*t.x - b*t.y;
        im += a*t.y + b*t.x;
    }
    int nb = f >> 5, ch = f & 31;
    int mode = (kxi*16 + ky)*8 + kz;
    unsigned o = ((unsigned)(nb*2048 + mode)*32u + ch)*2u;
    g_XF[o & MXF] = re; g_XF[(o + 1) & MXF] = im;
}

// Coalesced transpose-pack of REAL weights -> WP[n][mode][i][o]. grid 1024, block 256
__global__ void pack_t_r_k(const float* __restrict__ sw, long nsw) {
    __shared__ float st[32*129];
    int tid = threadIdx.x;
    int bid = blockIdx.x;
    int q = bid >> 8, i = (bid >> 3) & 31, m1 = bid & 7;
    const float scale = 1.0f / 262144.0f;
    long baseS = (long)(q*32 + i)*32768 + m1*128;
    for (int idx = tid; idx < 4096; idx += 256) {
        int o = idx >> 7, j = idx & 127;
        st[o*129 + j] = ldc(sw, baseS + (long)o*1024 + j, nsw) * scale;
    }
    __syncthreads();
    int kxi = m1 + (q & 1)*8;
    int kyb = (q >> 1)*8;
    unsigned baseT = (unsigned)kxi*131072u + (unsigned)i*32u;
    for (int idx = tid; idx < 4096; idx += 256) {
        int n = idx >> 11, m2 = (idx >> 8) & 7, m3 = (idx >> 5) & 7, o = idx & 31;
        unsigned T = (unsigned)n*2097152u + baseT + (unsigned)(kyb + m2)*8192u + (unsigned)m3*1024u + o;
        g_WP[T & MFZ] = st[o*129 + m2*16 + m3*2 + n];
    }
}

// Pack interleaved complex weights (fallback)
__global__ void pack_k(const float* __restrict__ sw, long nsw) {
    int idx = blockIdx.x * 256 + threadIdx.x;
    int o = idx & 31, i = (idx >> 5) & 31, mode = (idx >> 10) & 2047, n = idx >> 21;
    int kz = mode & 7, ky = (mode >> 3) & 15, kxi = mode >> 7;
    int q = (kxi >= 8 ? 1 : 0) + (ky >= 8 ? 2 : 0);
    int m1 = kxi & 7, m2 = ky & 7, m3 = kz;
    long src = ((((((long)q*32 + i)*32 + o)*8 + m1)*8 + m2)*8 + m3)*2 + n;
    const float scale = 1.0f / 262144.0f;
    g_WP[((unsigned)idx*2u) & MFZ]     = ldc(sw, src*2,     nsw) * scale;
    g_WP[((unsigned)idx*2u + 1) & MFZ] = ldc(sw, src*2 + 1, nsw) * scale;
}

// Pack split re/im planes (fallback)
__global__ void pack2_k(const float* __restrict__ swr, long nr,
                        const float* __restrict__ swi, long ni) {
    int idx = blockIdx.x * 256 + threadIdx.x;
    int o = idx & 31, i = (idx >> 5) & 31, mode = (idx >> 10) & 2047, n = idx >> 21;
    int kz = mode & 7, ky = (mode >> 3) & 15, kxi = mode >> 7;
    int q = (kxi >= 8 ? 1 : 0) + (ky >= 8 ? 2 : 0);
    int m1 = kxi & 7, m2 = ky & 7, m3 = kz;
    long src = ((((((long)q*32 + i)*32 + o)*8 + m1)*8 + m2)*8 + m3)*2 + n;
    const float scale = 1.0f / 262144.0f;
    g_WP[((unsigned)idx*2u) & MFZ]     = ldc(swr, src, nr) * scale;
    g_WP[((unsigned)idx*2u + 1) & MFZ] = ldc(swi, src, ni) * scale;
}

// Mode multiply, REAL weights + FFMA2. grid (2048,2), block 64
__global__ void modemul_r_k() {
    __shared__ __align__(16) float wsh[1024];
    __shared__ __align__(16) float xs[128];
    int tid = threadIdx.x;
    int mode = blockIdx.x, n = blockIdx.y;
    unsigned wslab = (unsigned)(n*2048 + mode) * 1024u;
    for (int i = tid; i < 1024; i += 64) wsh[i] = g_WP[(wslab + i) & MFZ];
    for (int idx = tid; idx < 128; idx += 64) {
        int b = idx >> 6, r = idx & 63;
        xs[idx] = g_XF[((unsigned)((n*2 + b)*2048 + mode)*64u + r) & MXF];
    }
    __syncthreads();
    int o = tid & 31, b = tid >> 5;
    const float* xv = xs + b*64;
    ull acc = pk(0.f, 0.f);
    #pragma unroll
    for (int i = 0; i < 32; i++) {
        float w = wsh[i*32 + o];
        ull x2 = *(const ull*)&xv[i*2];
        acc = fma2(x2, pk(w, w), acc);
    }
    float orr, oii; upk(acc, orr, oii);
    int kz = mode & 7, ky = (mode >> 3) & 15, kxi = mode >> 7;
    int nb = n*2 + b;
    unsigned addr = (((unsigned)(nb*32 + o)*8u + kz)*16u + ky)*32u + kxi;
    g_XO[addr & MXF] = orr;
    g_XO[(addr + 16) & MXF] = oii;
}

// Mode multiply, complex (fallback)
__global__ void modemul_k() {
    __shared__ float xs[128];
    __shared__ float2 wsh[1024];
    int tid = threadIdx.x;
    int mode = blockIdx.x, n = blockIdx.y;
    unsigned wslab = (unsigned)(n*2048 + mode) * 2048u;
    for (int i = tid; i < 1024; i += 64) {
        float2 wv;
        wv.x = g_WP[(wslab + (unsigned)i*2u) & MFZ];
        wv.y = g_WP[(wslab + (unsigned)i*2u + 1) & MFZ];
        wsh[i] = wv;
    }
    for (int idx = tid; idx < 128; idx += 64) {
        int b = idx >> 6, r = idx & 63;
        xs[idx] = g_XF[((unsigned)((n*2 + b)*2048 + mode)*64u + r) & MXF];
    }
    __syncthreads();
    int o = tid & 31, b = tid >> 5;
    const float* xv = xs + b*64;
    float orr = 0.f, oii = 0.f;
    #pragma unroll
    for (int i = 0; i < 32; i++) {
        float2 wv = wsh[i*32 + o];
        float xr = xv[i*2], xi = xv[i*2 + 1];
        orr += xr*wv.x - xi*wv.y;
        oii += xr*wv.y + xi*wv.x;
    }
    int kz = mode & 7, ky = (mode >> 3) & 15, kxi = mode >> 7;
    int nb = n*2 + b;
    unsigned addr = (((unsigned)(nb*32 + o)*8u + kz)*16u + ky)*32u + kxi;
    g_XO[addr & MXF] = orr;
    g_XO[(addr + 16) & MXF] = oii;
}

// Inverse X. grid (8,128), block 1024
__global__ __launch_bounds__(1024) void invx_k() {
    __shared__ float xsh[16*33];
    __shared__ float2 tw[1024];
    int tid = threadIdx.x;
    int kz = blockIdx.x, f2 = blockIdx.y;
    {   int x = tid >> 4, kxi = tid & 15;
        int kact = (kxi < 8) ? kxi : kxi - 16;
        float sv, cv; sincospif((float)(kact*x) * (1.0f/32.0f), &sv, &cv);
        tw[x*16 + kxi].x = cv; tw[x*16 + kxi].y = sv; }
    if (tid < 512) {
        int ky = tid >> 5, r = tid & 31;
        xsh[ky*33 + r] = g_XO[((unsigned)(f2*8 + kz)*512u + tid) & MXF];
    }
    __syncthreads();
    int x = tid >> 4, ky = tid & 15;
    float re = 0.f, im = 0.f;
    #pragma unroll
    for (int k = 0; k < 16; k++) {
        float a = xsh[ky*33 + k], b = xsh[ky*33 + 16 + k];
        float2 t = tw[x*16 + k];
        re += a*t.x - b*t.y;
        im += a*t.y + b*t.x;
    }
    unsigned o = ((unsigned)(f2*64 + x)*8u + kz)*32u + ky;
    g_GX[o & MFYZ] = re; g_GX[(o + 16) & MFYZ] = im;
}

// FUSED inverse Y + inverse Z + BN + residual + ReLU, FFMA2 invz. grid (64,128), block 512
__global__ void invyz_k(const float* __restrict__ gamma, long ng,
                        const float* __restrict__ beta, long nbt) {
    __shared__ float gsh[8*34];
    __shared__ float2 ty1[1024];
    __shared__ ull tileRe[64*9], tileIm[64*9];
    __shared__ ull tzc[8*33], tzs[8*33];
    __shared__ float sh_mean, sh_inv, sh_g, sh_b;
    int tid = threadIdx.x;
    int x = blockIdx.x, f2 = blockIdx.y;
    #pragma unroll
    for (int i = 0; i < 2; i++) {
        int idx = tid + i*512;
        int y = idx >> 4, ky = idx & 15;
        int kact = (ky < 8) ? ky : ky - 16;
        float sv, cv; sincospif((float)(kact*y) * (1.0f/32.0f), &sv, &cv);
        ty1[idx].x = cv; ty1[idx].y = sv;
    }
    if (tid < 256) {
        int k = tid >> 5, zp = tid & 31;
        int z0 = zp*2, z1 = z0 + 1;
        float s0, c0, s1v, c1v;
        sincospif((float)(k*z0) * (1.0f/32.0f), &s0, &c0);
        sincospif((float)(k*z1) * (1.0f/32.0f), &s1v, &c1v);
        tzc[k*33 + zp] = pk(2.0f*c0, 2.0f*c1v);
        tzs[k*33 + zp] = pk(-2.0f*s0, -2.0f*s1v);
    }
    if (tid < 256) {
        int kz = tid >> 5, r = tid & 31;
        int reim = r >> 4, ky = r & 15;
        gsh[kz*34 + reim*17 + ky] = g_GX[((unsigned)(f2*64 + x)*256u + tid) & MFYZ];
    }
    if (tid == 0) {
        int n = f2 >> 6, o = f2 & 31;
        double s1 = g_acc[((n*32 + o)*2) & 127], s2 = g_acc[((n*32 + o)*2 + 1) & 127];
        float mean = (float)(s1 * (1.0/BN_CNT));
        float var  = (float)(s2 * (1.0/BN_CNT)) - mean*mean;
        sh_mean = mean;
        sh_inv = rsqrtf(var + 1e-5f);
        sh_g = (o < ng)  ? gamma[o] : 1.0f;
        sh_b = (o < nbt) ? beta[o]  : 0.0f;
    }
    __syncthreads();
    {
        int y = tid >> 3, kz = tid & 7;
        float re = 0.f, im = 0.f;
        #pragma unroll
        for (int ky = 0; ky < 16; ky++) {
            float a = gsh[kz*34 + ky], b = gsh[kz*34 + 17 + ky];
            float2 t = ty1[y*16 + ky];
            re += a*t.x - b*t.y;
            im += a*t.y + b*t.x;
        }
        tileRe[y*9 + kz] = pk(re, re);
        tileIm[y*9 + kz] = pk(im, im);
    }
    __syncthreads();
    float mean = sh_mean, inv = sh_inv, gm = sh_g, bt = sh_b;
    int y = tid >> 3, zg = tid & 7;
    ull vp0, vp1, vp2, vp3;
    vp0 = vp1 = vp2 = vp3 = tileRe[y*9 + 0];
    int zpb = zg*4;
    #pragma unroll
    for (int k = 1; k < 8; k++) {
        ull A = tileRe[y*9 + k], B = tileIm[y*9 + k];
        vp0 = fma2(A, tzc[k*33 + zpb+0], vp0); vp0 = fma2(B, tzs[k*33 + zpb+0], vp0);
        vp1 = fma2(A, tzc[k*33 + zpb+1], vp1); vp1 = fma2(B, tzs[k*33 + zpb+1], vp1);
        vp2 = fma2(A, tzc[k*33 + zpb+2], vp2); vp2 = fma2(B, tzs[k*33 + zpb+2], vp2);
        vp3 = fma2(A, tzc[k*33 + zpb+3], vp3); vp3 = fma2(B, tzs[k*33 + zpb+3], vp3);
    }
    float vz[8];
    upk(vp0, vz[0], vz[1]); upk(vp1, vz[2], vz[3]);
    upk(vp2, vz[4], vz[5]); upk(vp3, vz[6], vz[7]);
    unsigned base = (unsigned)f2 * Sd + (unsigned)(x*4096 + y*64 + zg*8);
    float4 y0 = *(const float4*)&g_Y[base & MH];
    float4 y1 = *(const float4*)&g_Y[(base + 4) & MH];
    float4 o0, o1;
    o0.x = fmaxf(vz[0] + gm*(y0.x - mean)*inv + bt, 0.f);
    o0.y = fmaxf(vz[1] + gm*(y0.y - mean)*inv + bt, 0.f);
    o0.z = fmaxf(vz[2] + gm*(y0.z - mean)*inv + bt, 0.f);
    o0.w = fmaxf(vz[3] + gm*(y0.w - mean)*inv + bt, 0.f);
    o1.x = fmaxf(vz[4] + gm*(y1.x - mean)*inv + bt, 0.f);
    o1.y = fmaxf(vz[5] + gm*(y1.y - mean)*inv + bt, 0.f);
    o1.z = fmaxf(vz[6] + gm*(y1.z - mean)*inv + bt, 0.f);
    o1.w = fmaxf(vz[7] + gm*(y1.w - mean)*inv + bt, 0.f);
    *(float4*)&g_H[base & MH] = o0;
    *(float4*)&g_H[(base + 4) & MH] = o1;
}

// fc1(relu)+fc2 head, 2 points/thread, j16-block FFMA2
__global__ void fc12_k(const float* __restrict__ w1, long nw1,
                       const float* __restrict__ b1, long nb1,
                       const float* __restrict__ w2, long nw2,
                       const float* __restrict__ b2, long nb2,
                       float* __restrict__ out, int nOut) {
    __shared__ __align__(16) float w1s[4096];
    __shared__ __align__(16) float b1s[128];
    __shared__ __align__(16) float w2s[128];
    int tid = threadIdx.x;
    for (int i = tid; i < 4096; i += 256) w1s[i] = ldc(w1, i, nw1);
    if (tid < 128) { b1s[tid] = ldc(b1, tid, nb1); w2s[tid] = ldc(w2, tid, nw2); }
    __syncthreads();
    int t = blockIdx.x * 256 + tid;
    int p0 = t * 2;
    if (p0 >= nOut) return;
    int s = t & (Sd - 1), b = (t >> 18) & 1;
    unsigned base0 = (unsigned)((0*2 + b)*32) * Sd + (unsigned)s;
    unsigned base1 = (unsigned)((1*2 + b)*32) * Sd + (unsigned)s;
    float v0[32], v1[32];
    #pragma unroll
    for (int c = 0; c < 32; c++) {
        v0[c] = g_H[(base0 + (unsigned)c * Sd) & MH];
        v1[c] = g_H[(base1 + (unsigned)c * Sd) & MH];
    }
    float bias2 = (nb2 > 0) ? b2[0] : 0.0f;
    float acc0 = bias2, acc1 = bias2;
    #pragma unroll
    for (int jb = 0; jb < 8; jb++) {
        ull hp0[8], hp1[8];
        #pragma unroll
        for (int q = 0; q < 8; q++) {
            ull bq = *(const ull*)&b1s[jb*16 + q*2];
            hp0[q] = bq; hp1[q] = bq;
        }
        #pragma unroll
        for (int c = 0; c < 32; c++) {
            ull d0 = pk(v0[c], v0[c]), d1 = pk(v1[c], v1[c]);
            const ull* wrow = (const ull*)&w1s[c*128 + jb*16];
            #pragma unroll
            for (int q = 0; q < 8; q++) {
                ull wq = wrow[q];
                hp0[q] = fma2(d0, wq, hp0[q]);
                hp1[q] = fma2(d1, wq, hp1[q]);
            }
        }
        #pragma unroll
        for (int q = 0; q < 8; q++) {
            float h0a, h0b, h1a, h1b;
            upk(hp0[q], h0a, h0b);
            upk(hp1[q], h1a, h1b);
            float2 wv = *(const float2*)&w2s[jb*16 + q*2];
            acc0 += fmaxf(h0a, 0.f)*wv.x + fmaxf(h0b, 0.f)*wv.y;
            acc1 += fmaxf(h1a, 0.f)*wv.x + fmaxf(h1b, 0.f)*wv.y;
        }
    }
    out[p0] = acc0;
    if (p0 + 1 < nOut) out[p0 + 1] = acc1;
}

// ---------------- launch ----------------
extern "C" void kernel_launch(void* const* d_in, const int* in_sizes, int n_in,
                              void* d_out, int out_size) {
    bool bytesMode = false, sawElem = false;
    for (int i = 0; i < n_in; i++) {
        if (in_sizes[i] == 416)  sawElem = true;
        if (in_sizes[i] == 1664) bytesMode = true;
    }
    if (sawElem) bytesMode = false;

    long esz[64];
    int ncap = n_in < 64 ? n_in : 64;
    for (int i = 0; i < ncap; i++) {
        long s = (long)in_sizes[i];
        esz[i] = bytesMode ? s / 4 : s;
    }

    int idxX = -1, idxF0W = -1, idxF1W = -1, idxF2B = -1;
    int big[8]; int nbig = 0;
    int cw[4];  int ncw = 0;
    int s128[4]; int n128 = 0;
    int s32[12]; int n32 = 0;
    for (int i = 0; i < ncap; i++) {
        long s = esz[i];
        if (s > 10000000)      idxX = i;
        else if (s >= 2000000) { if (nbig < 8) big[nbig++] = i; }
        else if (s == 4096)    idxF1W = i;
        else if (s == 1024)    { if (ncw < 4) cw[ncw++] = i; }
        else if (s == 416)     idxF0W = i;
        else if (s == 128)     { if (n128 < 4) s128[n128++] = i; }
        else if (s == 32)      { if (n32 < 12) s32[n32++] = i; }
        else if (s == 1)       idxF2B = i;
    }

    bool ok = (idxX >= 0) && (idxF0W >= 0) && (idxF1W >= 0) && (idxF2B >= 0)
              && (nbig == 3 || nbig == 6) && (ncw >= 3) && (n128 >= 2) && (n32 >= 10);

    int iX, iF0W, iF0B, iSWa[3], iSWb[3], iCW[3], iCB[3], iG[3], iB[3], iF1W, iF1B, iF2W, iF2B;
    bool swSplit = false;

    if (!ok) {
        int cap = (n_in > 0) ? n_in - 1 : 0;
        #define CLP(v) ((v) > cap ? cap : (v))
        iX = CLP(0); iF0W = CLP(1); iF0B = CLP(2);
        iSWa[0] = CLP(3); iSWa[1] = CLP(4); iSWa[2] = CLP(5);
        iSWb[0] = iSWb[1] = iSWb[2] = CLP(3);
        iCW[0] = CLP(6); iCB[0] = CLP(7); iCW[1] = CLP(8); iCB[1] = CLP(9);
        iCW[2] = CLP(10); iCB[2] = CLP(11);
        iG[0] = CLP(12); iB[0] = CLP(13); iG[1] = CLP(14); iB[1] = CLP(15);
        iG[2] = CLP(16); iB[2] = CLP(17);
        iF1W = CLP(18); iF1B = CLP(19); iF2W = CLP(20); iF2B = CLP(21);
        #undef CLP
    } else {
        iX = idxX; iF0W = idxF0W; iF1W = idxF1W; iF2B = idxF2B;
        iF1B = s128[0]; iF2W = s128[1];
        iCW[0] = cw[0]; iCW[1] = cw[1]; iCW[2] = cw[2];
        bool sigOrder = (idxX == 0);
        if (sigOrder) {
            iF0B = s32[0];
            iCB[0] = s32[1]; iCB[1] = s32[2]; iCB[2] = s32[3];
            iG[0] = s32[4]; iB[0] = s32[5];
            iG[1] = s32[6]; iB[1] = s32[7];
            iG[2] = s32[8]; iB[2] = s32[9];
        } else {
            iB[0] = s32[0]; iB[1] = s32[1]; iB[2] = s32[2];
            iCB[0] = s32[3]; iCB[1] = s32[4]; iCB[2] = s32[5];
            iF0B = s32[6];
            iG[0] = s32[7]; iG[1] = s32[8]; iG[2] = s32[9];
        }
        swSplit = (nbig == 6);
        if (swSplit) {
            for (int k = 0; k < 3; k++) {
                if (sigOrder) { iSWa[k] = big[2*k]; iSWb[k] = big[2*k + 1]; }
                else          { iSWb[k] = big[2*k]; iSWa[k] = big[2*k + 1]; }
            }
        } else {
            for (int k = 0; k < 3; k++) { iSWa[k] = big[k]; iSWb[k] = big[k]; }
        }
    }

    #define PTR(i) ((const float*)d_in[i])
    #define ESZ(i) (esz[i])

    for (int k = 0; k < 3; k++) {
        bool realW = !swSplit && (ESZ(iSWa[k]) < 8000000);
        zero_acc_k<<<1, 128>>>();
        if (k == 0)
            fc0conv_k<<<2048, 256>>>(PTR(iX), ESZ(iX), PTR(iF0W), ESZ(iF0W),
                                     PTR(iF0B), ESZ(iF0B),
                                     PTR(iCW[0]), ESZ(iCW[0]), PTR(iCB[0]), ESZ(iCB[0]));
        else
            convB_k<<<dim3(512, 4), 256>>>(PTR(iCW[k]), ESZ(iCW[k]), PTR(iCB[k]), ESZ(iCB[k]));
        specz_k<<<dim3(32, 128), 512>>>();
        specy_k<<<dim3(8, 128), 256>>>();
        specx_k<<<dim3(16, 128), 128>>>();
        if (swSplit)       pack2_k<<<16384, 256>>>(PTR(iSWa[k]), ESZ(iSWa[k]), PTR(iSWb[k]), ESZ(iSWb[k]));
        else if (!realW)   pack_k<<<16384, 256>>>(PTR(iSWa[k]), ESZ(iSWa[k]));
        else               pack_t_r_k<<<1024, 256>>>(PTR(iSWa[k]), ESZ(iSWa[k]));
        if (realW) modemul_r_k<<<dim3(2048, 2), 64>>>();
        else       modemul_k<<<dim3(2048, 2), 64>>>();
        invx_k<<<dim3(8, 128), 1024>>>();
        invyz_k<<<dim3(64, 128), 512>>>(PTR(iG[k]), ESZ(iG[k]), PTR(iB[k]), ESZ(iB[k]));
    }

    long nOutL = (long)out_size;
    if (nOutL > 1048576) nOutL = 1048576;
    int nOut = (int)nOutL;
    if (nOut > 0)
        fc12_k<<<(nOut/2 + 255) / 256, 256>>>(PTR(iF1W), ESZ(iF1W), PTR(iF1B), ESZ(iF1B),
                                              PTR(iF2W), ESZ(iF2W), PTR(iF2B), ESZ(iF2B),
                                              (float*)d_out, nOut);
    #undef PTR
    #undef ESZ
}